// round 1
// baseline (speedup 1.0000x reference)
#include <cuda_runtime.h>

// Problem constants
#define B_DIM 32
#define N_DIM 2048
#define F_DIM 512
#define K_DIM 256
#define D_DIM 1024
#define M_MAIN (B_DIM * N_DIM)   // 65536

// GEMM tiling
#define BM 128
#define BN 128
#define BK 16
#define TM 8
#define TN 8
// threads = (BM/TM)*(BN/TN) = 256

// Scratch for the city embedding c[N, D] (8 MB). __device__ global per the
// allocation rules (no cudaMalloc anywhere).
__device__ float g_cbuf[N_DIM * D_DIM];

// C = A[M,K] @ B[Nd,K]^T (+ bias), with optional fused leaky_relu * gate epilogue.
// MODE 0: city embed  -> writes g_cbuf
// MODE 1: main embed  -> v = leaky(acc + bias) * g_cbuf[n_row, d]; writes C
template <int MODE>
__global__ __launch_bounds__(256) void sgemm_nt_fused(
    const float* __restrict__ A, const float* __restrict__ Bmat,
    const float* __restrict__ bias, float* __restrict__ C,
    int M, int Nd, int K)
{
    __shared__ float As[BK][BM];
    __shared__ float Bs[BK][BN];

    const int bm = blockIdx.y * BM;
    const int bn = blockIdx.x * BN;
    const int tid = threadIdx.x;
    const int tx = tid & 15;       // 0..15 -> column micro-tile
    const int ty = tid >> 4;       // 0..15 -> row micro-tile

    const float* Ab = A + (size_t)bm * K;
    const float* Bb = Bmat + (size_t)bn * K;

    float acc[TM][TN];
    #pragma unroll
    for (int i = 0; i < TM; i++)
        #pragma unroll
        for (int j = 0; j < TN; j++) acc[i][j] = 0.0f;

    for (int k0 = 0; k0 < K; k0 += BK) {
        // Load A tile (BM x BK): 512 float4 total, 2 per thread, stored transposed.
        #pragma unroll
        for (int i = 0; i < 2; i++) {
            int id = tid + i * 256;
            int r  = id >> 2;
            int c4 = (id & 3) << 2;
            float4 v = *(const float4*)(Ab + (size_t)r * K + k0 + c4);
            As[c4 + 0][r] = v.x; As[c4 + 1][r] = v.y;
            As[c4 + 2][r] = v.z; As[c4 + 3][r] = v.w;
        }
        // Load B tile (BN x BK), same pattern.
        #pragma unroll
        for (int i = 0; i < 2; i++) {
            int id = tid + i * 256;
            int r  = id >> 2;
            int c4 = (id & 3) << 2;
            float4 v = *(const float4*)(Bb + (size_t)r * K + k0 + c4);
            Bs[c4 + 0][r] = v.x; Bs[c4 + 1][r] = v.y;
            Bs[c4 + 2][r] = v.z; Bs[c4 + 3][r] = v.w;
        }
        __syncthreads();

        #pragma unroll
        for (int k = 0; k < BK; k++) {
            float ra[TM], rb[TN];
            // float4 reads to get LDS.128s
            float4 a0 = *(const float4*)&As[k][ty * TM];
            float4 a1 = *(const float4*)&As[k][ty * TM + 4];
            float4 b0 = *(const float4*)&Bs[k][tx * TN];
            float4 b1 = *(const float4*)&Bs[k][tx * TN + 4];
            ra[0] = a0.x; ra[1] = a0.y; ra[2] = a0.z; ra[3] = a0.w;
            ra[4] = a1.x; ra[5] = a1.y; ra[6] = a1.z; ra[7] = a1.w;
            rb[0] = b0.x; rb[1] = b0.y; rb[2] = b0.z; rb[3] = b0.w;
            rb[4] = b1.x; rb[5] = b1.y; rb[6] = b1.z; rb[7] = b1.w;
            #pragma unroll
            for (int i = 0; i < TM; i++)
                #pragma unroll
                for (int j = 0; j < TN; j++)
                    acc[i][j] = fmaf(ra[i], rb[j], acc[i][j]);
        }
        __syncthreads();
    }

    // Epilogue
    #pragma unroll
    for (int i = 0; i < TM; i++) {
        int m = bm + ty * TM + i;
        int n_row = m & (N_DIM - 1);   // m % 2048 (only used in MODE 1)
        #pragma unroll
        for (int j = 0; j < TN; j++) {
            int n = bn + tx * TN + j;
            float v = acc[i][j] + bias[n];
            if (MODE == 0) {
                g_cbuf[(size_t)m * D_DIM + n] = v;
            } else {
                v = (v >= 0.0f) ? v : 0.2f * v;              // leaky_relu(0.2)
                v *= g_cbuf[(size_t)n_row * D_DIM + n];      // gate by city embed
                C[(size_t)m * (size_t)Nd + n] = v;
            }
        }
    }
}

// In-place LayerNorm over the last dim (D=1024). One block per row,
// 256 threads, 4 floats (one float4) per thread.
__global__ __launch_bounds__(256) void ln_kernel(
    float* __restrict__ X,
    const float* __restrict__ gamma, const float* __restrict__ beta)
{
    __shared__ float red_s[8];
    __shared__ float red_ss[8];

    const size_t row = blockIdx.x;
    float* p = X + row * D_DIM;
    const int tid = threadIdx.x;

    float4 v = ((const float4*)p)[tid];
    float s  = v.x + v.y + v.z + v.w;
    float ss = v.x * v.x + v.y * v.y + v.z * v.z + v.w * v.w;

    #pragma unroll
    for (int o = 16; o > 0; o >>= 1) {
        s  += __shfl_xor_sync(0xFFFFFFFFu, s,  o);
        ss += __shfl_xor_sync(0xFFFFFFFFu, ss, o);
    }
    const int wid = tid >> 5, lid = tid & 31;
    if (lid == 0) { red_s[wid] = s; red_ss[wid] = ss; }
    __syncthreads();

    s = 0.0f; ss = 0.0f;
    #pragma unroll
    for (int w = 0; w < 8; w++) { s += red_s[w]; ss += red_ss[w]; }

    const float inv_d = 1.0f / (float)D_DIM;
    float mean = s * inv_d;
    float var  = ss * inv_d - mean * mean;
    float rstd = rsqrtf(var + 1e-5f);

    float4 g  = ((const float4*)gamma)[tid];
    float4 be = ((const float4*)beta)[tid];
    v.x = (v.x - mean) * rstd * g.x + be.x;
    v.y = (v.y - mean) * rstd * g.y + be.y;
    v.z = (v.z - mean) * rstd * g.z + be.z;
    v.w = (v.w - mean) * rstd * g.w + be.w;
    ((float4*)p)[tid] = v;
}

extern "C" void kernel_launch(void* const* d_in, const int* in_sizes, int n_in,
                              void* d_out, int out_size)
{
    const float* input  = (const float*)d_in[0];  // [B, N, F]
    const float* stat   = (const float*)d_in[1];  // [N, K]
    const float* W_feat = (const float*)d_in[2];  // [D, F]
    const float* b_feat = (const float*)d_in[3];  // [D]
    const float* W_city = (const float*)d_in[4];  // [D, K]
    const float* b_city = (const float*)d_in[5];  // [D]
    const float* gamma  = (const float*)d_in[6];  // [D]
    const float* beta   = (const float*)d_in[7];  // [D]
    float* out = (float*)d_out;                   // [B, N, D]

    // 1) c[N, D] = static @ W_city^T + b_city  -> g_cbuf
    {
        dim3 grid(D_DIM / BN, N_DIM / BM);
        sgemm_nt_fused<0><<<grid, 256>>>(stat, W_city, b_city, out,
                                         N_DIM, D_DIM, K_DIM);
    }
    // 2) out = leaky(input @ W_feat^T + b_feat) * c   (pre-LN values)
    {
        dim3 grid(D_DIM / BN, M_MAIN / BM);
        sgemm_nt_fused<1><<<grid, 256>>>(input, W_feat, b_feat, out,
                                         M_MAIN, D_DIM, F_DIM);
    }
    // 3) in-place LayerNorm over D
    {
        ln_kernel<<<M_MAIN, 256>>>(out, gamma, beta);
    }
}

// round 4
// speedup vs baseline: 2.7474x; 2.7474x over previous
#include <cuda_runtime.h>
#include <cstdint>

// Problem constants
#define B_DIM 32
#define N_DIM 2048
#define F_DIM 512
#define K_DIM 256
#define D_DIM 1024
#define M_MAIN (B_DIM * N_DIM)   // 65536

// Scratch for the city embedding c[N, D] (8 MB). __device__ global (no cudaMalloc).
__device__ float g_cbuf[N_DIM * D_DIM];

// ---------------------------------------------------------------------------
// helpers
// ---------------------------------------------------------------------------
__device__ __forceinline__ uint32_t smem_u32(const void* p) {
    uint32_t a;
    asm("{ .reg .u64 t; cvta.to.shared.u64 t, %1; cvt.u32.u64 %0, t; }"
        : "=r"(a) : "l"(p));
    return a;
}

__device__ __forceinline__ void cp_async16(uint32_t dst, const void* src) {
    asm volatile("cp.async.cg.shared.global [%0], [%1], 16;"
                 :: "r"(dst), "l"(src) : "memory");
}

__device__ __forceinline__ uint32_t f2tf32(float f) {
    uint32_t u;
    asm("cvt.rna.tf32.f32 %0, %1;" : "=r"(u) : "f"(f));
    return u;
}

__device__ __forceinline__ void mma_tf32(float& c0, float& c1, float& c2, float& c3,
                                         uint32_t a0, uint32_t a1, uint32_t a2, uint32_t a3,
                                         uint32_t b0, uint32_t b1) {
    asm volatile(
        "mma.sync.aligned.m16n8k8.row.col.f32.tf32.tf32.f32 "
        "{%0,%1,%2,%3}, {%4,%5,%6,%7}, {%8,%9}, {%0,%1,%2,%3};"
        : "+f"(c0), "+f"(c1), "+f"(c2), "+f"(c3)
        : "r"(a0), "r"(a1), "r"(a2), "r"(a3), "r"(b0), "r"(b1));
}

// ---------------------------------------------------------------------------
// Main GEMM (tf32 mma.sync): out = leaky(input @ W_feat^T + b_feat) * gate
// BM=128, BN=128, BK=32, 8 warps (32x64 warp tiles), cp.async double buffer.
// SMEM row stride = 36 floats (== 4 mod 32 -> conflict-free fragment LDS).
// ---------------------------------------------------------------------------
#define BM_T 128
#define BN_T 128
#define BK_T 32
#define NCHUNK (F_DIM / BK_T)       // 16
#define LDS_STRIDE 36               // floats per SMEM row
#define A_FLOATS (BM_T * LDS_STRIDE)            // 4608
#define B_FLOATS (BN_T * LDS_STRIDE)            // 4608
#define STAGE_FLOATS (A_FLOATS + B_FLOATS)      // 9216
#define SMEM_MAIN_BYTES (2 * STAGE_FLOATS * 4)  // 73728

__global__ __launch_bounds__(256, 2) void main_gemm_mma(
    const float* __restrict__ A,     // [M_MAIN, F]
    const float* __restrict__ W,     // [D, F]
    const float* __restrict__ bias,  // [D]
    float* __restrict__ out)         // [M_MAIN, D]
{
    extern __shared__ float smem[];
    const int tid  = threadIdx.x;
    const int wid  = tid >> 5;
    const int lane = tid & 31;
    const int wm   = wid & 3;        // warp row  (32 rows each)
    const int wn   = wid >> 2;       // warp col  (64 cols each)
    const int g    = lane >> 2;      // fragment row group 0..7
    const int t    = lane & 3;       // fragment k group   0..3

    const int bm = blockIdx.y * BM_T;
    const int bn = blockIdx.x * BN_T;

    const float* Arow = A + (size_t)bm * F_DIM;
    const float* Wrow = W + (size_t)bn * F_DIM;

    const uint32_t smem_b = smem_u32(smem);

    float acc[2][8][4];
    #pragma unroll
    for (int i = 0; i < 2; i++)
        #pragma unroll
        for (int j = 0; j < 8; j++)
            #pragma unroll
            for (int c = 0; c < 4; c++) acc[i][j][c] = 0.0f;

    // cp.async slot assignment: 1024 16B-chunks per tile side, 4 per thread.
    // id = tid + 256*s : row = id>>3, c16 = id&7.
    auto prefetch = [&](int k0, int buf) {
        float* stg = smem + buf * STAGE_FLOATS;
        const uint32_t a_s = smem_b + (uint32_t)(buf * STAGE_FLOATS) * 4u;
        const uint32_t b_s = a_s + A_FLOATS * 4u;
        #pragma unroll
        for (int s = 0; s < 4; s++) {
            int id = tid + s * 256;
            int r  = id >> 3;
            int c16 = id & 7;
            cp_async16(a_s + (uint32_t)(r * LDS_STRIDE + c16 * 4) * 4u,
                       Arow + (size_t)r * F_DIM + k0 + c16 * 4);
        }
        #pragma unroll
        for (int s = 0; s < 4; s++) {
            int id = tid + s * 256;
            int r  = id >> 3;
            int c16 = id & 7;
            cp_async16(b_s + (uint32_t)(r * LDS_STRIDE + c16 * 4) * 4u,
                       Wrow + (size_t)r * F_DIM + k0 + c16 * 4);
        }
        (void)stg;
    };

    prefetch(0, 0);
    asm volatile("cp.async.commit_group;" ::: "memory");

    for (int k = 0; k < NCHUNK; k++) {
        const int buf = k & 1;
        if (k + 1 < NCHUNK) {
            prefetch((k + 1) * BK_T, buf ^ 1);
            asm volatile("cp.async.commit_group;" ::: "memory");
            asm volatile("cp.async.wait_group 1;" ::: "memory");
        } else {
            asm volatile("cp.async.wait_group 0;" ::: "memory");
        }
        __syncthreads();

        const float* As = smem + buf * STAGE_FLOATS;
        const float* Bs = As + A_FLOATS;

        #pragma unroll
        for (int ks = 0; ks < 4; ks++) {
            const int kk = ks * 8 + t;
            // A fragments for the two m16 tiles
            uint32_t af[2][4];
            #pragma unroll
            for (int i = 0; i < 2; i++) {
                const float* ap = As + (wm * 32 + i * 16 + g) * LDS_STRIDE + kk;
                af[i][0] = f2tf32(ap[0]);
                af[i][1] = f2tf32(ap[8 * LDS_STRIDE]);
                af[i][2] = f2tf32(ap[4]);
                af[i][3] = f2tf32(ap[8 * LDS_STRIDE + 4]);
            }
            // B fragments + MMAs for the eight n8 tiles
            #pragma unroll
            for (int j = 0; j < 8; j++) {
                const float* bp = Bs + (wn * 64 + j * 8 + g) * LDS_STRIDE + kk;
                uint32_t b0 = f2tf32(bp[0]);
                uint32_t b1 = f2tf32(bp[4]);
                #pragma unroll
                for (int i = 0; i < 2; i++)
                    mma_tf32(acc[i][j][0], acc[i][j][1], acc[i][j][2], acc[i][j][3],
                             af[i][0], af[i][1], af[i][2], af[i][3], b0, b1);
            }
        }
        __syncthreads();
    }

    // Fused epilogue: +bias -> leaky_relu(0.2) -> * gate(g_cbuf) -> out
    #pragma unroll
    for (int i = 0; i < 2; i++) {
        #pragma unroll
        for (int half = 0; half < 2; half++) {   // c0c1 (row g) / c2c3 (row g+8)
            const int m = bm + wm * 32 + i * 16 + g + half * 8;
            const float* gate = g_cbuf + (size_t)(m & (N_DIM - 1)) * D_DIM;
            float* orow = out + (size_t)m * D_DIM;
            #pragma unroll
            for (int j = 0; j < 8; j++) {
                const int n = bn + wn * 64 + j * 8 + 2 * t;
                float v0 = acc[i][j][half * 2 + 0] + __ldg(bias + n);
                float v1 = acc[i][j][half * 2 + 1] + __ldg(bias + n + 1);
                v0 = (v0 >= 0.0f) ? v0 : 0.2f * v0;
                v1 = (v1 >= 0.0f) ? v1 : 0.2f * v1;
                float2 o;
                o.x = v0 * __ldg(gate + n);
                o.y = v1 * __ldg(gate + n + 1);
                *(float2*)(orow + n) = o;
            }
        }
    }
}

// ---------------------------------------------------------------------------
// City embed GEMM (fp32 scalar, small): g_cbuf = static @ W_city^T + b_city
// ---------------------------------------------------------------------------
#define BM 128
#define BN 128
#define BKC 16
#define TM 8
#define TN 8

__global__ __launch_bounds__(256) void city_gemm(
    const float* __restrict__ A, const float* __restrict__ Bmat,
    const float* __restrict__ bias, int K)
{
    __shared__ float As[BKC][BM];
    __shared__ float Bs[BKC][BN];

    const int bm = blockIdx.y * BM;
    const int bn = blockIdx.x * BN;
    const int tid = threadIdx.x;
    const int tx = tid & 15;
    const int ty = tid >> 4;

    const float* Ab = A + (size_t)bm * K;
    const float* Bb = Bmat + (size_t)bn * K;

    float acc[TM][TN];
    #pragma unroll
    for (int i = 0; i < TM; i++)
        #pragma unroll
        for (int j = 0; j < TN; j++) acc[i][j] = 0.0f;

    for (int k0 = 0; k0 < K; k0 += BKC) {
        #pragma unroll
        for (int i = 0; i < 2; i++) {
            int id = tid + i * 256;
            int r  = id >> 2;
            int c4 = (id & 3) << 2;
            float4 v = *(const float4*)(Ab + (size_t)r * K + k0 + c4);
            As[c4 + 0][r] = v.x; As[c4 + 1][r] = v.y;
            As[c4 + 2][r] = v.z; As[c4 + 3][r] = v.w;
        }
        #pragma unroll
        for (int i = 0; i < 2; i++) {
            int id = tid + i * 256;
            int r  = id >> 2;
            int c4 = (id & 3) << 2;
            float4 v = *(const float4*)(Bb + (size_t)r * K + k0 + c4);
            Bs[c4 + 0][r] = v.x; Bs[c4 + 1][r] = v.y;
            Bs[c4 + 2][r] = v.z; Bs[c4 + 3][r] = v.w;
        }
        __syncthreads();

        #pragma unroll
        for (int k = 0; k < BKC; k++) {
            float ra[TM], rb[TN];
            float4 a0 = *(const float4*)&As[k][ty * TM];
            float4 a1 = *(const float4*)&As[k][ty * TM + 4];
            float4 b0 = *(const float4*)&Bs[k][tx * TN];
            float4 b1 = *(const float4*)&Bs[k][tx * TN + 4];
            ra[0] = a0.x; ra[1] = a0.y; ra[2] = a0.z; ra[3] = a0.w;
            ra[4] = a1.x; ra[5] = a1.y; ra[6] = a1.z; ra[7] = a1.w;
            rb[0] = b0.x; rb[1] = b0.y; rb[2] = b0.z; rb[3] = b0.w;
            rb[4] = b1.x; rb[5] = b1.y; rb[6] = b1.z; rb[7] = b1.w;
            #pragma unroll
            for (int i = 0; i < TM; i++)
                #pragma unroll
                for (int j = 0; j < TN; j++)
                    acc[i][j] = fmaf(ra[i], rb[j], acc[i][j]);
        }
        __syncthreads();
    }

    #pragma unroll
    for (int i = 0; i < TM; i++) {
        int m = bm + ty * TM + i;
        #pragma unroll
        for (int j = 0; j < TN; j++) {
            int n = bn + tx * TN + j;
            g_cbuf[(size_t)m * D_DIM + n] = acc[i][j] + bias[n];
        }
    }
}

// ---------------------------------------------------------------------------
// In-place LayerNorm over D=1024. One block per row, 256 threads.
// ---------------------------------------------------------------------------
__global__ __launch_bounds__(256) void ln_kernel(
    float* __restrict__ X,
    const float* __restrict__ gamma, const float* __restrict__ beta)
{
    __shared__ float red_s[8];
    __shared__ float red_ss[8];

    const size_t row = blockIdx.x;
    float* p = X + row * D_DIM;
    const int tid = threadIdx.x;

    float4 v = ((const float4*)p)[tid];
    float s  = v.x + v.y + v.z + v.w;
    float ss = v.x * v.x + v.y * v.y + v.z * v.z + v.w * v.w;

    #pragma unroll
    for (int o = 16; o > 0; o >>= 1) {
        s  += __shfl_xor_sync(0xFFFFFFFFu, s,  o);
        ss += __shfl_xor_sync(0xFFFFFFFFu, ss, o);
    }
    const int wid = tid >> 5, lid = tid & 31;
    if (lid == 0) { red_s[wid] = s; red_ss[wid] = ss; }
    __syncthreads();

    s = 0.0f; ss = 0.0f;
    #pragma unroll
    for (int w = 0; w < 8; w++) { s += red_s[w]; ss += red_ss[w]; }

    const float inv_d = 1.0f / (float)D_DIM;
    float mean = s * inv_d;
    float var  = ss * inv_d - mean * mean;
    float rstd = rsqrtf(var + 1e-5f);

    float4 g  = ((const float4*)gamma)[tid];
    float4 be = ((const float4*)beta)[tid];
    v.x = (v.x - mean) * rstd * g.x + be.x;
    v.y = (v.y - mean) * rstd * g.y + be.y;
    v.z = (v.z - mean) * rstd * g.z + be.z;
    v.w = (v.w - mean) * rstd * g.w + be.w;
    ((float4*)p)[tid] = v;
}

// ---------------------------------------------------------------------------
extern "C" void kernel_launch(void* const* d_in, const int* in_sizes, int n_in,
                              void* d_out, int out_size)
{
    const float* input  = (const float*)d_in[0];  // [B, N, F]
    const float* stat   = (const float*)d_in[1];  // [N, K]
    const float* W_feat = (const float*)d_in[2];  // [D, F]
    const float* b_feat = (const float*)d_in[3];  // [D]
    const float* W_city = (const float*)d_in[4];  // [D, K]
    const float* b_city = (const float*)d_in[5];  // [D]
    const float* gamma  = (const float*)d_in[6];  // [D]
    const float* beta   = (const float*)d_in[7];  // [D]
    float* out = (float*)d_out;                   // [B, N, D]

    cudaFuncSetAttribute(main_gemm_mma,
                         cudaFuncAttributeMaxDynamicSharedMemorySize,
                         SMEM_MAIN_BYTES);

    // 1) city embed: g_cbuf = static @ W_city^T + b_city  (fp32 scalar)
    {
        dim3 grid(D_DIM / BN, N_DIM / BM);
        city_gemm<<<grid, 256>>>(stat, W_city, b_city, K_DIM);
    }
    // 2) main embed (tf32 mma.sync): out = leaky(input @ W_feat^T + b) * gate
    {
        dim3 grid(D_DIM / BN_T, M_MAIN / BM_T);  // (8, 512)
        main_gemm_mma<<<grid, 256, SMEM_MAIN_BYTES>>>(input, W_feat, b_feat, out);
    }
    // 3) in-place LayerNorm over D
    {
        ln_kernel<<<M_MAIN, 256>>>(out, gamma, beta);
    }
}

// round 5
// speedup vs baseline: 3.1738x; 1.1552x over previous
#include <cuda_runtime.h>
#include <cstdint>

// Problem constants
#define B_DIM 32
#define N_DIM 2048
#define F_DIM 512
#define K_DIM 256
#define D_DIM 1024
#define M_MAIN (B_DIM * N_DIM)   // 65536

// Scratch for the city embedding c[N, D] (8 MB). __device__ global (no cudaMalloc).
__device__ float g_cbuf[N_DIM * D_DIM];

// ---------------------------------------------------------------------------
// helpers
// ---------------------------------------------------------------------------
__device__ __forceinline__ uint32_t smem_u32(const void* p) {
    uint32_t a;
    asm("{ .reg .u64 t; cvta.to.shared.u64 t, %1; cvt.u32.u64 %0, t; }"
        : "=r"(a) : "l"(p));
    return a;
}

__device__ __forceinline__ void cp_async16(uint32_t dst, const void* src) {
    asm volatile("cp.async.cg.shared.global [%0], [%1], 16;"
                 :: "r"(dst), "l"(src) : "memory");
}

__device__ __forceinline__ uint32_t f2tf32(float f) {
    uint32_t u;
    asm("cvt.rna.tf32.f32 %0, %1;" : "=r"(u) : "f"(f));
    return u;
}

__device__ __forceinline__ void mma_tf32(float& c0, float& c1, float& c2, float& c3,
                                         uint32_t a0, uint32_t a1, uint32_t a2, uint32_t a3,
                                         uint32_t b0, uint32_t b1) {
    asm volatile(
        "mma.sync.aligned.m16n8k8.row.col.f32.tf32.tf32.f32 "
        "{%0,%1,%2,%3}, {%4,%5,%6,%7}, {%8,%9}, {%0,%1,%2,%3};"
        : "+f"(c0), "+f"(c1), "+f"(c2), "+f"(c3)
        : "r"(a0), "r"(a1), "r"(a2), "r"(a3), "r"(b0), "r"(b1));
}

// ---------------------------------------------------------------------------
// tf32 mma GEMM: C = A[M,KD] @ W[Nd,KD]^T + bias, with:
//   MODE 0 (city): writes g_cbuf[m*D + n] = acc + bias[n]
//   MODE 1 (main): writes out[m*D + n]   = leaky_relu(acc + bias[n], 0.2)
// BM=128, BN=128, BK=32, 8 warps (32x64 warp tiles), 3-stage cp.async.
// SMEM row stride = 36 floats (== 4 mod 32 -> conflict-free fragment LDS).
// ---------------------------------------------------------------------------
#define BM_T 128
#define BN_T 128
#define BK_T 32
#define LDS_STRIDE 36
#define A_FLOATS (BM_T * LDS_STRIDE)            // 4608
#define B_FLOATS (BN_T * LDS_STRIDE)            // 4608
#define STAGE_FLOATS (A_FLOATS + B_FLOATS)      // 9216
#define NSTAGE 3
#define SMEM_MAIN_BYTES (NSTAGE * STAGE_FLOATS * 4)  // 110592

template <int KD, int MODE>
__global__ __launch_bounds__(256, 2) void gemm_mma(
    const float* __restrict__ A,     // [M, KD]
    const float* __restrict__ W,     // [Nd, KD]
    const float* __restrict__ bias,  // [Nd]
    float* __restrict__ out)         // [M, D_DIM] (MODE 1) / unused (MODE 0)
{
    constexpr int NCHUNK = KD / BK_T;

    extern __shared__ float smem[];
    const int tid  = threadIdx.x;
    const int wid  = tid >> 5;
    const int lane = tid & 31;
    const int wm   = wid & 3;        // warp row  (32 rows each)
    const int wn   = wid >> 2;       // warp col  (64 cols each)
    const int g    = lane >> 2;      // fragment row group 0..7
    const int t    = lane & 3;       // fragment k group   0..3

    const int bm = blockIdx.y * BM_T;
    const int bn = blockIdx.x * BN_T;

    const float* Arow = A + (size_t)bm * KD;
    const float* Wrow = W + (size_t)bn * KD;

    const uint32_t smem_b = smem_u32(smem);

    float acc[2][8][4];
    #pragma unroll
    for (int i = 0; i < 2; i++)
        #pragma unroll
        for (int j = 0; j < 8; j++)
            #pragma unroll
            for (int c = 0; c < 4; c++) acc[i][j][c] = 0.0f;

    auto prefetch = [&](int k0, int buf) {
        const uint32_t a_s = smem_b + (uint32_t)(buf * STAGE_FLOATS) * 4u;
        const uint32_t b_s = a_s + A_FLOATS * 4u;
        #pragma unroll
        for (int s = 0; s < 4; s++) {
            int id = tid + s * 256;
            int r  = id >> 3;
            int c16 = id & 7;
            cp_async16(a_s + (uint32_t)(r * LDS_STRIDE + c16 * 4) * 4u,
                       Arow + (size_t)r * KD + k0 + c16 * 4);
        }
        #pragma unroll
        for (int s = 0; s < 4; s++) {
            int id = tid + s * 256;
            int r  = id >> 3;
            int c16 = id & 7;
            cp_async16(b_s + (uint32_t)(r * LDS_STRIDE + c16 * 4) * 4u,
                       Wrow + (size_t)r * KD + k0 + c16 * 4);
        }
    };

    prefetch(0, 0);
    asm volatile("cp.async.commit_group;" ::: "memory");
    prefetch(BK_T, 1);
    asm volatile("cp.async.commit_group;" ::: "memory");

    #pragma unroll
    for (int k = 0; k < NCHUNK; k++) {
        if (k + 2 < NCHUNK) {
            prefetch((k + 2) * BK_T, (k + 2) % NSTAGE);
            asm volatile("cp.async.commit_group;" ::: "memory");
            asm volatile("cp.async.wait_group 2;" ::: "memory");
        } else if (k + 1 < NCHUNK) {
            asm volatile("cp.async.wait_group 1;" ::: "memory");
        } else {
            asm volatile("cp.async.wait_group 0;" ::: "memory");
        }
        __syncthreads();

        const float* As = smem + (k % NSTAGE) * STAGE_FLOATS;
        const float* Bs = As + A_FLOATS;

        #pragma unroll
        for (int ks = 0; ks < 4; ks++) {
            const int kk = ks * 8 + t;
            uint32_t af[2][4];
            #pragma unroll
            for (int i = 0; i < 2; i++) {
                const float* ap = As + (wm * 32 + i * 16 + g) * LDS_STRIDE + kk;
                af[i][0] = f2tf32(ap[0]);
                af[i][1] = f2tf32(ap[8 * LDS_STRIDE]);
                af[i][2] = f2tf32(ap[4]);
                af[i][3] = f2tf32(ap[8 * LDS_STRIDE + 4]);
            }
            #pragma unroll
            for (int j = 0; j < 8; j++) {
                const float* bp = Bs + (wn * 64 + j * 8 + g) * LDS_STRIDE + kk;
                uint32_t b0 = f2tf32(bp[0]);
                uint32_t b1 = f2tf32(bp[4]);
                #pragma unroll
                for (int i = 0; i < 2; i++)
                    mma_tf32(acc[i][j][0], acc[i][j][1], acc[i][j][2], acc[i][j][3],
                             af[i][0], af[i][1], af[i][2], af[i][3], b0, b1);
            }
        }
        __syncthreads();
    }

    // Epilogue
    #pragma unroll
    for (int i = 0; i < 2; i++) {
        #pragma unroll
        for (int half = 0; half < 2; half++) {   // c0c1 (row g) / c2c3 (row g+8)
            const int m = bm + wm * 32 + i * 16 + g + half * 8;
            float* orow = (MODE == 0 ? (float*)g_cbuf : out) + (size_t)m * D_DIM;
            #pragma unroll
            for (int j = 0; j < 8; j++) {
                const int n = bn + wn * 64 + j * 8 + 2 * t;
                float v0 = acc[i][j][half * 2 + 0] + __ldg(bias + n);
                float v1 = acc[i][j][half * 2 + 1] + __ldg(bias + n + 1);
                if (MODE == 1) {
                    v0 = (v0 >= 0.0f) ? v0 : 0.2f * v0;
                    v1 = (v1 >= 0.0f) ? v1 : 0.2f * v1;
                }
                float2 o; o.x = v0; o.y = v1;
                *(float2*)(orow + n) = o;
            }
        }
    }
}

// ---------------------------------------------------------------------------
// Gate + LayerNorm over D=1024, in place on out.
//   y = out[row] * g_cbuf[row % N]; out[row] = LN(y) * gamma + beta
// One block per row, 256 threads, float4 per thread.
// ---------------------------------------------------------------------------
__global__ __launch_bounds__(256) void ln_gate_kernel(
    float* __restrict__ X,
    const float* __restrict__ gamma, const float* __restrict__ beta)
{
    __shared__ float red_s[8];
    __shared__ float red_ss[8];

    const size_t row = blockIdx.x;
    const size_t nrow = row & (N_DIM - 1);
    float* p = X + row * D_DIM;
    const float* gp = g_cbuf + nrow * D_DIM;
    const int tid = threadIdx.x;

    float4 v = ((const float4*)p)[tid];
    float4 c = ((const float4*)gp)[tid];
    v.x *= c.x; v.y *= c.y; v.z *= c.z; v.w *= c.w;

    float s  = v.x + v.y + v.z + v.w;
    float ss = v.x * v.x + v.y * v.y + v.z * v.z + v.w * v.w;

    #pragma unroll
    for (int o = 16; o > 0; o >>= 1) {
        s  += __shfl_xor_sync(0xFFFFFFFFu, s,  o);
        ss += __shfl_xor_sync(0xFFFFFFFFu, ss, o);
    }
    const int wid = tid >> 5, lid = tid & 31;
    if (lid == 0) { red_s[wid] = s; red_ss[wid] = ss; }
    __syncthreads();

    s = 0.0f; ss = 0.0f;
    #pragma unroll
    for (int w = 0; w < 8; w++) { s += red_s[w]; ss += red_ss[w]; }

    const float inv_d = 1.0f / (float)D_DIM;
    float mean = s * inv_d;
    float var  = ss * inv_d - mean * mean;
    float rstd = rsqrtf(var + 1e-5f);

    float4 gm = ((const float4*)gamma)[tid];
    float4 be = ((const float4*)beta)[tid];
    v.x = (v.x - mean) * rstd * gm.x + be.x;
    v.y = (v.y - mean) * rstd * gm.y + be.y;
    v.z = (v.z - mean) * rstd * gm.z + be.z;
    v.w = (v.w - mean) * rstd * gm.w + be.w;
    ((float4*)p)[tid] = v;
}

// ---------------------------------------------------------------------------
extern "C" void kernel_launch(void* const* d_in, const int* in_sizes, int n_in,
                              void* d_out, int out_size)
{
    const float* input  = (const float*)d_in[0];  // [B, N, F]
    const float* stat   = (const float*)d_in[1];  // [N, K]
    const float* W_feat = (const float*)d_in[2];  // [D, F]
    const float* b_feat = (const float*)d_in[3];  // [D]
    const float* W_city = (const float*)d_in[4];  // [D, K]
    const float* b_city = (const float*)d_in[5];  // [D]
    const float* gamma  = (const float*)d_in[6];  // [D]
    const float* beta   = (const float*)d_in[7];  // [D]
    float* out = (float*)d_out;                   // [B, N, D]

    cudaFuncSetAttribute(gemm_mma<F_DIM, 1>,
                         cudaFuncAttributeMaxDynamicSharedMemorySize,
                         SMEM_MAIN_BYTES);
    cudaFuncSetAttribute(gemm_mma<K_DIM, 0>,
                         cudaFuncAttributeMaxDynamicSharedMemorySize,
                         SMEM_MAIN_BYTES);

    // 1) main embed (tf32 mma): out = leaky(input @ W_feat^T + b_feat)
    //    Launched FIRST (no dependency on city now) so ncu profiles it.
    {
        dim3 grid(D_DIM / BN_T, M_MAIN / BM_T);  // (8, 512)
        gemm_mma<F_DIM, 1><<<grid, 256, SMEM_MAIN_BYTES>>>(input, W_feat, b_feat, out);
    }
    // 2) city embed (tf32 mma): g_cbuf = static @ W_city^T + b_city
    {
        dim3 grid(D_DIM / BN_T, N_DIM / BM_T);   // (8, 16)
        gemm_mma<K_DIM, 0><<<grid, 256, SMEM_MAIN_BYTES>>>(stat, W_city, b_city, nullptr);
    }
    // 3) gate + LayerNorm in place
    {
        ln_gate_kernel<<<M_MAIN, 256>>>(out, gamma, beta);
    }
}

// round 7
// speedup vs baseline: 3.3094x; 1.0428x over previous
#include <cuda_runtime.h>
#include <cstdint>

// Problem constants
#define B_DIM 32
#define N_DIM 2048
#define F_DIM 512
#define K_DIM 256
#define D_DIM 1024
#define M_MAIN (B_DIM * N_DIM)   // 65536

// __device__ scratch (no cudaMalloc allowed anywhere).
__device__ float g_cbuf[N_DIM * D_DIM];          // city embedding c[N, D]   (8 MB)
__device__ float g_a32[M_MAIN * F_DIM];          // tf32-rounded input       (128 MB)
__device__ float g_wf32[D_DIM * F_DIM];          // tf32-rounded W_feat      (2 MB)
__device__ float g_st32[N_DIM * K_DIM];          // tf32-rounded static      (2 MB)
__device__ float g_wc32[D_DIM * K_DIM];          // tf32-rounded W_city      (1 MB)

// ---------------------------------------------------------------------------
// helpers
// ---------------------------------------------------------------------------
__device__ __forceinline__ uint32_t smem_u32(const void* p) {
    uint32_t a;
    asm("{ .reg .u64 t; cvta.to.shared.u64 t, %1; cvt.u32.u64 %0, t; }"
        : "=r"(a) : "l"(p));
    return a;
}

__device__ __forceinline__ void cp_async16(uint32_t dst, const void* src) {
    asm volatile("cp.async.cg.shared.global [%0], [%1], 16;"
                 :: "r"(dst), "l"(src) : "memory");
}

__device__ __forceinline__ float f2tf32f(float f) {
    uint32_t u;
    asm("cvt.rna.tf32.f32 %0, %1;" : "=r"(u) : "f"(f));
    return __uint_as_float(u);
}

__device__ __forceinline__ void mma_tf32(float& c0, float& c1, float& c2, float& c3,
                                         uint32_t a0, uint32_t a1, uint32_t a2, uint32_t a3,
                                         uint32_t b0, uint32_t b1) {
    asm volatile(
        "mma.sync.aligned.m16n8k8.row.col.f32.tf32.tf32.f32 "
        "{%0,%1,%2,%3}, {%4,%5,%6,%7}, {%8,%9}, {%0,%1,%2,%3};"
        : "+f"(c0), "+f"(c1), "+f"(c2), "+f"(c3)
        : "r"(a0), "r"(a1), "r"(a2), "r"(a3), "r"(b0), "r"(b1));
}

// ---------------------------------------------------------------------------
// tf32-rounding pre-pass: dst[i] = round_tf32(src[i]).
// ---------------------------------------------------------------------------
__global__ __launch_bounds__(256) void tf32_round_kernel(
    const float* __restrict__ src, float* __restrict__ dst, int n4)
{
    int i = blockIdx.x * 1024 + threadIdx.x;
    #pragma unroll
    for (int s = 0; s < 4; s++) {
        int idx = i + s * 256;
        if (idx < n4) {
            float4 v = ((const float4*)src)[idx];
            v.x = f2tf32f(v.x); v.y = f2tf32f(v.y);
            v.z = f2tf32f(v.z); v.w = f2tf32f(v.w);
            ((float4*)dst)[idx] = v;
        }
    }
}

// ---------------------------------------------------------------------------
// tf32 mma GEMM on pre-rounded operands (no in-loop CVT):
//   MODE 0 (city): g_cbuf[m*D + n] = acc + bias[n]
//   MODE 1 (main): out[m*D + n]    = leaky_relu(acc + bias[n], 0.2)
// BM=128, BN=128, BK=32, 8 warps (32x64 warp tiles), 3-stage cp.async.
// One __syncthreads per chunk, placed AFTER cp.async.wait_group so that
// (a) all threads' chunk-k tiles are visible and (b) every warp has finished
// computing chunk k-1 before its stage ((k-1)%3 == (k+2)%3) is overwritten.
// SMEM row stride 36 floats (== 4 mod 32 -> conflict-free fragment LDS).
// ---------------------------------------------------------------------------
#define BM_T 128
#define BN_T 128
#define BK_T 32
#define LDS_STRIDE 36
#define A_FLOATS (BM_T * LDS_STRIDE)            // 4608
#define B_FLOATS (BN_T * LDS_STRIDE)            // 4608
#define STAGE_FLOATS (A_FLOATS + B_FLOATS)      // 9216
#define NSTAGE 3
#define SMEM_MAIN_BYTES (NSTAGE * STAGE_FLOATS * 4)  // 110592

template <int KD, int MODE>
__global__ __launch_bounds__(256, 2) void gemm_mma(
    const float* __restrict__ A,     // [M, KD]  tf32-rounded
    const float* __restrict__ W,     // [Nd, KD] tf32-rounded
    const float* __restrict__ bias,  // [Nd]
    float* __restrict__ out)         // [M, D_DIM] (MODE 1) / unused (MODE 0)
{
    constexpr int NCHUNK = KD / BK_T;

    extern __shared__ float smem[];
    const int tid  = threadIdx.x;
    const int wid  = tid >> 5;
    const int lane = tid & 31;
    const int wm   = wid & 3;        // warp row  (32 rows each)
    const int wn   = wid >> 2;       // warp col  (64 cols each)
    const int g    = lane >> 2;      // fragment row group 0..7
    const int t    = lane & 3;       // fragment k group   0..3

    const int bm = blockIdx.y * BM_T;
    const int bn = blockIdx.x * BN_T;

    const float* Arow = A + (size_t)bm * KD;
    const float* Wrow = W + (size_t)bn * KD;

    const uint32_t smem_b = smem_u32(smem);

    float acc[2][8][4];
    #pragma unroll
    for (int i = 0; i < 2; i++)
        #pragma unroll
        for (int j = 0; j < 8; j++)
            #pragma unroll
            for (int c = 0; c < 4; c++) acc[i][j][c] = 0.0f;

    auto prefetch = [&](int k0, int buf) {
        const uint32_t a_s = smem_b + (uint32_t)(buf * STAGE_FLOATS) * 4u;
        const uint32_t b_s = a_s + A_FLOATS * 4u;
        #pragma unroll
        for (int s = 0; s < 4; s++) {
            int id = tid + s * 256;
            int r  = id >> 3;
            int c16 = id & 7;
            cp_async16(a_s + (uint32_t)(r * LDS_STRIDE + c16 * 4) * 4u,
                       Arow + (size_t)r * KD + k0 + c16 * 4);
        }
        #pragma unroll
        for (int s = 0; s < 4; s++) {
            int id = tid + s * 256;
            int r  = id >> 3;
            int c16 = id & 7;
            cp_async16(b_s + (uint32_t)(r * LDS_STRIDE + c16 * 4) * 4u,
                       Wrow + (size_t)r * KD + k0 + c16 * 4);
        }
    };

    prefetch(0, 0);
    asm volatile("cp.async.commit_group;" ::: "memory");
    prefetch(BK_T, 1);
    asm volatile("cp.async.commit_group;" ::: "memory");

    #pragma unroll
    for (int k = 0; k < NCHUNK; k++) {
        // Ensure MY chunk-k group completed...
        if (k + 1 < NCHUNK) {
            asm volatile("cp.async.wait_group 1;" ::: "memory");
        } else {
            asm volatile("cp.async.wait_group 0;" ::: "memory");
        }
        // ...then one barrier: everyone's chunk-k data visible AND all warps
        // are past compute of k-1, freeing stage (k+2)%3 for the prefetch.
        __syncthreads();

        if (k + 2 < NCHUNK) {
            prefetch((k + 2) * BK_T, (k + 2) % NSTAGE);
            asm volatile("cp.async.commit_group;" ::: "memory");
        }

        const float* As = smem + (k % NSTAGE) * STAGE_FLOATS;
        const float* Bs = As + A_FLOATS;

        #pragma unroll
        for (int ks = 0; ks < 4; ks++) {
            const int kk = ks * 8 + t;
            uint32_t af[2][4];
            #pragma unroll
            for (int i = 0; i < 2; i++) {
                const float* ap = As + (wm * 32 + i * 16 + g) * LDS_STRIDE + kk;
                af[i][0] = __float_as_uint(ap[0]);
                af[i][1] = __float_as_uint(ap[8 * LDS_STRIDE]);
                af[i][2] = __float_as_uint(ap[4]);
                af[i][3] = __float_as_uint(ap[8 * LDS_STRIDE + 4]);
            }
            #pragma unroll
            for (int j = 0; j < 8; j++) {
                const float* bp = Bs + (wn * 64 + j * 8 + g) * LDS_STRIDE + kk;
                uint32_t b0 = __float_as_uint(bp[0]);
                uint32_t b1 = __float_as_uint(bp[4]);
                #pragma unroll
                for (int i = 0; i < 2; i++)
                    mma_tf32(acc[i][j][0], acc[i][j][1], acc[i][j][2], acc[i][j][3],
                             af[i][0], af[i][1], af[i][2], af[i][3], b0, b1);
            }
        }
    }

    // Epilogue
    #pragma unroll
    for (int i = 0; i < 2; i++) {
        #pragma unroll
        for (int half = 0; half < 2; half++) {   // c0c1 (row g) / c2c3 (row g+8)
            const int m = bm + wm * 32 + i * 16 + g + half * 8;
            float* orow = (MODE == 0 ? (float*)g_cbuf : out) + (size_t)m * D_DIM;
            #pragma unroll
            for (int j = 0; j < 8; j++) {
                const int n = bn + wn * 64 + j * 8 + 2 * t;
                float v0 = acc[i][j][half * 2 + 0] + __ldg(bias + n);
                float v1 = acc[i][j][half * 2 + 1] + __ldg(bias + n + 1);
                if (MODE == 1) {
                    v0 = (v0 >= 0.0f) ? v0 : 0.2f * v0;
                    v1 = (v1 >= 0.0f) ? v1 : 0.2f * v1;
                }
                float2 o; o.x = v0; o.y = v1;
                *(float2*)(orow + n) = o;
            }
        }
    }
}

// ---------------------------------------------------------------------------
// Gate + LayerNorm over D=1024, in place on out.
//   y = out[row] * g_cbuf[row % N]; out[row] = LN(y) * gamma + beta
// ---------------------------------------------------------------------------
__global__ __launch_bounds__(256) void ln_gate_kernel(
    float* __restrict__ X,
    const float* __restrict__ gamma, const float* __restrict__ beta)
{
    __shared__ float red_s[8];
    __shared__ float red_ss[8];

    const size_t row = blockIdx.x;
    const size_t nrow = row & (N_DIM - 1);
    float* p = X + row * D_DIM;
    const float* gp = g_cbuf + nrow * D_DIM;
    const int tid = threadIdx.x;

    float4 v = ((const float4*)p)[tid];
    float4 c = ((const float4*)gp)[tid];
    v.x *= c.x; v.y *= c.y; v.z *= c.z; v.w *= c.w;

    float s  = v.x + v.y + v.z + v.w;
    float ss = v.x * v.x + v.y * v.y + v.z * v.z + v.w * v.w;

    #pragma unroll
    for (int o = 16; o > 0; o >>= 1) {
        s  += __shfl_xor_sync(0xFFFFFFFFu, s,  o);
        ss += __shfl_xor_sync(0xFFFFFFFFu, ss, o);
    }
    const int wid = tid >> 5, lid = tid & 31;
    if (lid == 0) { red_s[wid] = s; red_ss[wid] = ss; }
    __syncthreads();

    s = 0.0f; ss = 0.0f;
    #pragma unroll
    for (int w = 0; w < 8; w++) { s += red_s[w]; ss += red_ss[w]; }

    const float inv_d = 1.0f / (float)D_DIM;
    float mean = s * inv_d;
    float var  = ss * inv_d - mean * mean;
    float rstd = rsqrtf(var + 1e-5f);

    float4 gm = ((const float4*)gamma)[tid];
    float4 be = ((const float4*)beta)[tid];
    v.x = (v.x - mean) * rstd * gm.x + be.x;
    v.y = (v.y - mean) * rstd * gm.y + be.y;
    v.z = (v.z - mean) * rstd * gm.z + be.z;
    v.w = (v.w - mean) * rstd * gm.w + be.w;
    ((float4*)p)[tid] = v;
}

// ---------------------------------------------------------------------------
extern "C" void kernel_launch(void* const* d_in, const int* in_sizes, int n_in,
                              void* d_out, int out_size)
{
    const float* input  = (const float*)d_in[0];  // [B, N, F]
    const float* stat   = (const float*)d_in[1];  // [N, K]
    const float* W_feat = (const float*)d_in[2];  // [D, F]
    const float* b_feat = (const float*)d_in[3];  // [D]
    const float* W_city = (const float*)d_in[4];  // [D, K]
    const float* b_city = (const float*)d_in[5];  // [D]
    const float* gamma  = (const float*)d_in[6];  // [D]
    const float* beta   = (const float*)d_in[7];  // [D]
    float* out = (float*)d_out;                   // [B, N, D]

    cudaFuncSetAttribute(gemm_mma<F_DIM, 1>,
                         cudaFuncAttributeMaxDynamicSharedMemorySize,
                         SMEM_MAIN_BYTES);
    cudaFuncSetAttribute(gemm_mma<K_DIM, 0>,
                         cudaFuncAttributeMaxDynamicSharedMemorySize,
                         SMEM_MAIN_BYTES);

    float *a32, *wf32, *st32, *wc32;
    cudaGetSymbolAddress((void**)&a32,  g_a32);
    cudaGetSymbolAddress((void**)&wf32, g_wf32);
    cudaGetSymbolAddress((void**)&st32, g_st32);
    cudaGetSymbolAddress((void**)&wc32, g_wc32);

    // 0) tf32-rounding pre-passes (bit-identical to converting at use time).
    {
        int n4 = (M_MAIN * F_DIM) / 4;   // 8388608
        tf32_round_kernel<<<(n4 + 1023) / 1024, 256>>>(input, a32, n4);
        n4 = (D_DIM * F_DIM) / 4;
        tf32_round_kernel<<<(n4 + 1023) / 1024, 256>>>(W_feat, wf32, n4);
        n4 = (N_DIM * K_DIM) / 4;
        tf32_round_kernel<<<(n4 + 1023) / 1024, 256>>>(stat, st32, n4);
        n4 = (D_DIM * K_DIM) / 4;
        tf32_round_kernel<<<(n4 + 1023) / 1024, 256>>>(W_city, wc32, n4);
    }
    // 1) main embed (tf32 mma): out = leaky(input @ W_feat^T + b_feat)
    {
        dim3 grid(D_DIM / BN_T, M_MAIN / BM_T);  // (8, 512)
        gemm_mma<F_DIM, 1><<<grid, 256, SMEM_MAIN_BYTES>>>(a32, wf32, b_feat, out);
    }
    // 2) city embed (tf32 mma): g_cbuf = static @ W_city^T + b_city
    {
        dim3 grid(D_DIM / BN_T, N_DIM / BM_T);   // (8, 16)
        gemm_mma<K_DIM, 0><<<grid, 256, SMEM_MAIN_BYTES>>>(st32, wc32, b_city, nullptr);
    }
    // 3) gate + LayerNorm in place
    {
        ln_gate_kernel<<<M_MAIN, 256>>>(out, gamma, beta);
    }
}

// round 8
// speedup vs baseline: 5.0195x; 1.5167x over previous
#include <cuda_runtime.h>
#include <cuda_fp16.h>
#include <cstdint>

// Problem constants
#define B_DIM 32
#define N_DIM 2048
#define F_DIM 512
#define K_DIM 256
#define D_DIM 1024
#define M_MAIN (B_DIM * N_DIM)   // 65536

// __device__ scratch (no cudaMalloc allowed anywhere).
__device__ float  g_cbuf[N_DIM * D_DIM];   // city embedding c[N, D]  (8 MB)
__device__ __half g_a16[M_MAIN * F_DIM];   // fp16 input              (64 MB)
__device__ __half g_wf16[D_DIM * F_DIM];   // fp16 W_feat             (1 MB)
__device__ __half g_st16[N_DIM * K_DIM];   // fp16 static             (1 MB)
__device__ __half g_wc16[D_DIM * K_DIM];   // fp16 W_city             (0.5 MB)

// ---------------------------------------------------------------------------
// helpers
// ---------------------------------------------------------------------------
__device__ __forceinline__ uint32_t smem_u32(const void* p) {
    uint32_t a;
    asm("{ .reg .u64 t; cvta.to.shared.u64 t, %1; cvt.u32.u64 %0, t; }"
        : "=r"(a) : "l"(p));
    return a;
}

__device__ __forceinline__ void cp_async16(uint32_t dst, const void* src) {
    asm volatile("cp.async.cg.shared.global [%0], [%1], 16;"
                 :: "r"(dst), "l"(src) : "memory");
}

// fp16 HMMA, fp32 accumulate: D(16x8) += A(16x16) * B(16x8)
__device__ __forceinline__ void mma_f16(float& c0, float& c1, float& c2, float& c3,
                                        uint32_t a0, uint32_t a1, uint32_t a2, uint32_t a3,
                                        uint32_t b0, uint32_t b1) {
    asm volatile(
        "mma.sync.aligned.m16n8k16.row.col.f32.f16.f16.f32 "
        "{%0,%1,%2,%3}, {%4,%5,%6,%7}, {%8,%9}, {%0,%1,%2,%3};"
        : "+f"(c0), "+f"(c1), "+f"(c2), "+f"(c3)
        : "r"(a0), "r"(a1), "r"(a2), "r"(a3), "r"(b0), "r"(b1));
}

// ---------------------------------------------------------------------------
// fp32 -> fp16 conversion pre-pass (round-to-nearest). n4 = n/4.
// ---------------------------------------------------------------------------
__global__ __launch_bounds__(256) void f2h_kernel(
    const float* __restrict__ src, __half* __restrict__ dst, int n4)
{
    int i = blockIdx.x * 1024 + threadIdx.x;
    #pragma unroll
    for (int s = 0; s < 4; s++) {
        int idx = i + s * 256;
        if (idx < n4) {
            float4 v = ((const float4*)src)[idx];
            __half2 h0 = __floats2half2_rn(v.x, v.y);
            __half2 h1 = __floats2half2_rn(v.z, v.w);
            uint2 u;
            u.x = *(uint32_t*)&h0;
            u.y = *(uint32_t*)&h1;
            ((uint2*)dst)[idx] = u;
        }
    }
}

// ---------------------------------------------------------------------------
// fp16 mma GEMM (fp32 accumulate): C = A[M,KD] @ W[Nd,KD]^T + bias
//   MODE 0 (city): g_cbuf[m*D + n] = acc + bias[n]
//   MODE 1 (main): out[m*D + n]    = leaky_relu(acc + bias[n], 0.2)
// BM=128, BN=128, BK=64 halves, 8 warps (32x64 warp tiles), 3-stage cp.async.
// SMEM row stride = 72 halves = 36 words; fragment LDS bank = (4g+t+8ks)%32,
// a perfect permutation -> conflict-free.
// ---------------------------------------------------------------------------
#define BM_T 128
#define BN_T 128
#define BK_T 64                              // K elements per chunk
#define STRIDE_W 36                          // uint32 words per SMEM row
#define A_WORDS (BM_T * STRIDE_W)            // 4608
#define B_WORDS (BN_T * STRIDE_W)            // 4608
#define STAGE_WORDS (A_WORDS + B_WORDS)      // 9216
#define NSTAGE 3
#define SMEM_MAIN_BYTES (NSTAGE * STAGE_WORDS * 4)  // 110592

template <int KD, int MODE>
__global__ __launch_bounds__(256, 2) void gemm_mma(
    const __half* __restrict__ A,    // [M, KD]  fp16
    const __half* __restrict__ W,    // [Nd, KD] fp16
    const float* __restrict__ bias,  // [Nd]
    float* __restrict__ out)         // [M, D_DIM] (MODE 1) / unused (MODE 0)
{
    constexpr int NCHUNK = KD / BK_T;

    extern __shared__ uint32_t smem[];
    const int tid  = threadIdx.x;
    const int wid  = tid >> 5;
    const int lane = tid & 31;
    const int wm   = wid & 3;        // warp row  (32 rows each)
    const int wn   = wid >> 2;       // warp col  (64 cols each)
    const int g    = lane >> 2;      // fragment row group 0..7
    const int t    = lane & 3;       // fragment k group   0..3

    const int bm = blockIdx.y * BM_T;
    const int bn = blockIdx.x * BN_T;

    const __half* Arow = A + (size_t)bm * KD;
    const __half* Wrow = W + (size_t)bn * KD;

    const uint32_t smem_b = smem_u32(smem);

    float acc[2][8][4];
    #pragma unroll
    for (int i = 0; i < 2; i++)
        #pragma unroll
        for (int j = 0; j < 8; j++)
            #pragma unroll
            for (int c = 0; c < 4; c++) acc[i][j][c] = 0.0f;

    // Per stage side: 128 rows x 64 halves = 128B/row = 8 x 16B chunks
    // -> 1024 cp.async per side, 4 per thread.
    auto prefetch = [&](int k0, int buf) {
        const uint32_t a_s = smem_b + (uint32_t)(buf * STAGE_WORDS) * 4u;
        const uint32_t b_s = a_s + A_WORDS * 4u;
        #pragma unroll
        for (int s = 0; s < 4; s++) {
            int id = tid + s * 256;
            int r  = id >> 3;
            int c16 = id & 7;
            cp_async16(a_s + (uint32_t)(r * 144 + c16 * 16),
                       Arow + (size_t)r * KD + k0 + c16 * 8);
        }
        #pragma unroll
        for (int s = 0; s < 4; s++) {
            int id = tid + s * 256;
            int r  = id >> 3;
            int c16 = id & 7;
            cp_async16(b_s + (uint32_t)(r * 144 + c16 * 16),
                       Wrow + (size_t)r * KD + k0 + c16 * 8);
        }
    };

    prefetch(0, 0);
    asm volatile("cp.async.commit_group;" ::: "memory");
    prefetch(BK_T, 1);
    asm volatile("cp.async.commit_group;" ::: "memory");

    #pragma unroll
    for (int k = 0; k < NCHUNK; k++) {
        // My chunk-k group done...
        if (k + 1 < NCHUNK) {
            asm volatile("cp.async.wait_group 1;" ::: "memory");
        } else {
            asm volatile("cp.async.wait_group 0;" ::: "memory");
        }
        // ...then one barrier: everyone's chunk-k data visible AND all warps
        // past compute of k-1, freeing stage (k+2)%3 for the prefetch.
        __syncthreads();

        if (k + 2 < NCHUNK) {
            prefetch((k + 2) * BK_T, (k + 2) % NSTAGE);
            asm volatile("cp.async.commit_group;" ::: "memory");
        }

        const uint32_t* As32 = smem + (k % NSTAGE) * STAGE_WORDS;
        const uint32_t* Bs32 = As32 + A_WORDS;

        #pragma unroll
        for (int ks = 0; ks < 4; ks++) {       // 4 k16 steps per chunk
            uint32_t af[2][4];
            #pragma unroll
            for (int i = 0; i < 2; i++) {
                const uint32_t* ap = As32 + (wm * 32 + i * 16 + g) * STRIDE_W
                                   + ks * 8 + t;
                af[i][0] = ap[0];                   // (row g,   k 2t..2t+1)
                af[i][1] = ap[8 * STRIDE_W];        // (row g+8, k 2t..2t+1)
                af[i][2] = ap[4];                   // (row g,   k 2t+8..2t+9)
                af[i][3] = ap[8 * STRIDE_W + 4];    // (row g+8, k 2t+8..2t+9)
            }
            #pragma unroll
            for (int j = 0; j < 8; j++) {
                const uint32_t* bp = Bs32 + (wn * 64 + j * 8 + g) * STRIDE_W
                                   + ks * 8 + t;
                uint32_t b0 = bp[0];
                uint32_t b1 = bp[4];
                #pragma unroll
                for (int i = 0; i < 2; i++)
                    mma_f16(acc[i][j][0], acc[i][j][1], acc[i][j][2], acc[i][j][3],
                            af[i][0], af[i][1], af[i][2], af[i][3], b0, b1);
            }
        }
    }

    // Epilogue
    #pragma unroll
    for (int i = 0; i < 2; i++) {
        #pragma unroll
        for (int half = 0; half < 2; half++) {   // c0c1 (row g) / c2c3 (row g+8)
            const int m = bm + wm * 32 + i * 16 + g + half * 8;
            float* orow = (MODE == 0 ? (float*)g_cbuf : out) + (size_t)m * D_DIM;
            #pragma unroll
            for (int j = 0; j < 8; j++) {
                const int n = bn + wn * 64 + j * 8 + 2 * t;
                float v0 = acc[i][j][half * 2 + 0] + __ldg(bias + n);
                float v1 = acc[i][j][half * 2 + 1] + __ldg(bias + n + 1);
                if (MODE == 1) {
                    v0 = (v0 >= 0.0f) ? v0 : 0.2f * v0;
                    v1 = (v1 >= 0.0f) ? v1 : 0.2f * v1;
                }
                float2 o; o.x = v0; o.y = v1;
                *(float2*)(orow + n) = o;
            }
        }
    }
}

// ---------------------------------------------------------------------------
// Gate + LayerNorm over D=1024, in place on out.
//   y = out[row] * g_cbuf[row % N]; out[row] = LN(y) * gamma + beta
// ---------------------------------------------------------------------------
__global__ __launch_bounds__(256) void ln_gate_kernel(
    float* __restrict__ X,
    const float* __restrict__ gamma, const float* __restrict__ beta)
{
    __shared__ float red_s[8];
    __shared__ float red_ss[8];

    const size_t row = blockIdx.x;
    const size_t nrow = row & (N_DIM - 1);
    float* p = X + row * D_DIM;
    const float* gp = g_cbuf + nrow * D_DIM;
    const int tid = threadIdx.x;

    float4 v = ((const float4*)p)[tid];
    float4 c = ((const float4*)gp)[tid];
    v.x *= c.x; v.y *= c.y; v.z *= c.z; v.w *= c.w;

    float s  = v.x + v.y + v.z + v.w;
    float ss = v.x * v.x + v.y * v.y + v.z * v.z + v.w * v.w;

    #pragma unroll
    for (int o = 16; o > 0; o >>= 1) {
        s  += __shfl_xor_sync(0xFFFFFFFFu, s,  o);
        ss += __shfl_xor_sync(0xFFFFFFFFu, ss, o);
    }
    const int wid = tid >> 5, lid = tid & 31;
    if (lid == 0) { red_s[wid] = s; red_ss[wid] = ss; }
    __syncthreads();

    s = 0.0f; ss = 0.0f;
    #pragma unroll
    for (int w = 0; w < 8; w++) { s += red_s[w]; ss += red_ss[w]; }

    const float inv_d = 1.0f / (float)D_DIM;
    float mean = s * inv_d;
    float var  = ss * inv_d - mean * mean;
    float rstd = rsqrtf(var + 1e-5f);

    float4 gm = ((const float4*)gamma)[tid];
    float4 be = ((const float4*)beta)[tid];
    v.x = (v.x - mean) * rstd * gm.x + be.x;
    v.y = (v.y - mean) * rstd * gm.y + be.y;
    v.z = (v.z - mean) * rstd * gm.z + be.z;
    v.w = (v.w - mean) * rstd * gm.w + be.w;
    ((float4*)p)[tid] = v;
}

// ---------------------------------------------------------------------------
extern "C" void kernel_launch(void* const* d_in, const int* in_sizes, int n_in,
                              void* d_out, int out_size)
{
    const float* input  = (const float*)d_in[0];  // [B, N, F]
    const float* stat   = (const float*)d_in[1];  // [N, K]
    const float* W_feat = (const float*)d_in[2];  // [D, F]
    const float* b_feat = (const float*)d_in[3];  // [D]
    const float* W_city = (const float*)d_in[4];  // [D, K]
    const float* b_city = (const float*)d_in[5];  // [D]
    const float* gamma  = (const float*)d_in[6];  // [D]
    const float* beta   = (const float*)d_in[7];  // [D]
    float* out = (float*)d_out;                   // [B, N, D]

    cudaFuncSetAttribute(gemm_mma<F_DIM, 1>,
                         cudaFuncAttributeMaxDynamicSharedMemorySize,
                         SMEM_MAIN_BYTES);
    cudaFuncSetAttribute(gemm_mma<K_DIM, 0>,
                         cudaFuncAttributeMaxDynamicSharedMemorySize,
                         SMEM_MAIN_BYTES);

    __half *a16, *wf16, *st16, *wc16;
    cudaGetSymbolAddress((void**)&a16,  g_a16);
    cudaGetSymbolAddress((void**)&wf16, g_wf16);
    cudaGetSymbolAddress((void**)&st16, g_st16);
    cudaGetSymbolAddress((void**)&wc16, g_wc16);

    // 0) fp32 -> fp16 pre-passes (fp16 mantissa == tf32 mantissa: 11 bits)
    {
        int n4 = (M_MAIN * F_DIM) / 4;   // 8388608
        f2h_kernel<<<(n4 + 1023) / 1024, 256>>>(input, a16, n4);
        n4 = (D_DIM * F_DIM) / 4;
        f2h_kernel<<<(n4 + 1023) / 1024, 256>>>(W_feat, wf16, n4);
        n4 = (N_DIM * K_DIM) / 4;
        f2h_kernel<<<(n4 + 1023) / 1024, 256>>>(stat, st16, n4);
        n4 = (D_DIM * K_DIM) / 4;
        f2h_kernel<<<(n4 + 1023) / 1024, 256>>>(W_city, wc16, n4);
    }
    // 1) main embed (fp16 mma, fp32 accum): out = leaky(input @ W_feat^T + b)
    {
        dim3 grid(D_DIM / BN_T, M_MAIN / BM_T);  // (8, 512)
        gemm_mma<F_DIM, 1><<<grid, 256, SMEM_MAIN_BYTES>>>(a16, wf16, b_feat, out);
    }
    // 2) city embed (fp16 mma): g_cbuf = static @ W_city^T + b_city
    {
        dim3 grid(D_DIM / BN_T, N_DIM / BM_T);   // (8, 16)
        gemm_mma<K_DIM, 0><<<grid, 256, SMEM_MAIN_BYTES>>>(st16, wc16, b_city, nullptr);
    }
    // 3) gate + LayerNorm in place
    {
        ln_gate_kernel<<<M_MAIN, 256>>>(out, gamma, beta);
    }
}

// round 10
// speedup vs baseline: 5.0830x; 1.0126x over previous
#include <cuda_runtime.h>
#include <cuda_fp16.h>
#include <cstdint>

// Problem constants
#define B_DIM 32
#define N_DIM 2048
#define F_DIM 512
#define K_DIM 256
#define D_DIM 1024
#define M_MAIN (B_DIM * N_DIM)   // 65536

// __device__ scratch (no cudaMalloc allowed anywhere).
__device__ float  g_cbuf[N_DIM * D_DIM];   // city embedding c[N, D]  (8 MB)
__device__ __half g_a16[M_MAIN * F_DIM];   // fp16 input              (64 MB)
__device__ __half g_wf16[D_DIM * F_DIM];   // fp16 W_feat             (1 MB)
__device__ __half g_st16[N_DIM * K_DIM];   // fp16 static             (1 MB)
__device__ __half g_wc16[D_DIM * K_DIM];   // fp16 W_city             (0.5 MB)

// ---------------------------------------------------------------------------
// helpers
// ---------------------------------------------------------------------------
__device__ __forceinline__ uint32_t smem_u32(const void* p) {
    uint32_t a;
    asm("{ .reg .u64 t; cvta.to.shared.u64 t, %1; cvt.u32.u64 %0, t; }"
        : "=r"(a) : "l"(p));
    return a;
}

__device__ __forceinline__ void cp_async16(uint32_t dst, const void* src) {
    asm volatile("cp.async.cg.shared.global [%0], [%1], 16;"
                 :: "r"(dst), "l"(src) : "memory");
}

__device__ __forceinline__ void mma_f16(float& c0, float& c1, float& c2, float& c3,
                                        uint32_t a0, uint32_t a1, uint32_t a2, uint32_t a3,
                                        uint32_t b0, uint32_t b1) {
    asm volatile(
        "mma.sync.aligned.m16n8k16.row.col.f32.f16.f16.f32 "
        "{%0,%1,%2,%3}, {%4,%5,%6,%7}, {%8,%9}, {%0,%1,%2,%3};"
        : "+f"(c0), "+f"(c1), "+f"(c2), "+f"(c3)
        : "r"(a0), "r"(a1), "r"(a2), "r"(a3), "r"(b0), "r"(b1));
}

#define CLUSTER_ARRIVE() asm volatile("barrier.cluster.arrive.aligned;" ::: "memory")
#define CLUSTER_WAIT()   asm volatile("barrier.cluster.wait.aligned;" ::: "memory")

__device__ __forceinline__ uint32_t cluster_rank() {
    uint32_t r;
    asm("mov.u32 %0, %%cluster_ctarank;" : "=r"(r));
    return r;
}

// Store (s, ss) to the same smem offset in cluster CTA `rank`.
__device__ __forceinline__ void dsmem_st_f32x2(uint32_t local_addr, uint32_t rank,
                                               float s, float ss) {
    uint64_t pk;
    asm("mov.b64 %0, {%1, %2};" : "=l"(pk) : "f"(s), "f"(ss));
    uint32_t rem;
    asm("mapa.shared::cluster.u32 %0, %1, %2;" : "=r"(rem) : "r"(local_addr), "r"(rank));
    asm volatile("st.shared::cluster.b64 [%0], %1;" :: "r"(rem), "l"(pk) : "memory");
}

// ---------------------------------------------------------------------------
// fp32 -> fp16 pre-passes
// ---------------------------------------------------------------------------
__global__ __launch_bounds__(256) void f2h_kernel(
    const float* __restrict__ src, __half* __restrict__ dst, int n4)
{
    int i = blockIdx.x * 1024 + threadIdx.x;
    #pragma unroll
    for (int s = 0; s < 4; s++) {
        int idx = i + s * 256;
        if (idx < n4) {
            float4 v = ((const float4*)src)[idx];
            __half2 h0 = __floats2half2_rn(v.x, v.y);
            __half2 h1 = __floats2half2_rn(v.z, v.w);
            uint2 u;
            u.x = *(uint32_t*)&h0;
            u.y = *(uint32_t*)&h1;
            ((uint2*)dst)[idx] = u;
        }
    }
}

// All three weight tensors in one launch (each region is a multiple of 4 floats).
#define WF_N4 (D_DIM * F_DIM / 4)   // 131072
#define ST_N4 (N_DIM * K_DIM / 4)   // 131072
#define WC_N4 (D_DIM * K_DIM / 4)   // 65536
__global__ __launch_bounds__(256) void f2h3_kernel(
    const float* __restrict__ s1, __half* __restrict__ d1,
    const float* __restrict__ s2, __half* __restrict__ d2,
    const float* __restrict__ s3, __half* __restrict__ d3)
{
    int i = blockIdx.x * 1024 + threadIdx.x;
    #pragma unroll
    for (int s = 0; s < 4; s++) {
        int idx = i + s * 256;
        const float* src; __half* dst; int off;
        if (idx < WF_N4)                    { src = s1; dst = d1; off = idx; }
        else if (idx < WF_N4 + ST_N4)       { src = s2; dst = d2; off = idx - WF_N4; }
        else if (idx < WF_N4 + ST_N4 + WC_N4) { src = s3; dst = d3; off = idx - WF_N4 - ST_N4; }
        else continue;
        float4 v = ((const float4*)src)[off];
        __half2 h0 = __floats2half2_rn(v.x, v.y);
        __half2 h1 = __floats2half2_rn(v.z, v.w);
        uint2 u;
        u.x = *(uint32_t*)&h0;
        u.y = *(uint32_t*)&h1;
        ((uint2*)dst)[off] = u;
    }
}

// ---------------------------------------------------------------------------
// Shared GEMM tiling constants (fp16 operands, fp32 accum)
// ---------------------------------------------------------------------------
#define BM_T 128
#define BN_T 128
#define BK_T 64                              // K elements per chunk
#define STRIDE_W 36                          // uint32 words per SMEM row
#define A_WORDS (BM_T * STRIDE_W)            // 4608
#define B_WORDS (BN_T * STRIDE_W)            // 4608
#define STAGE_WORDS (A_WORDS + B_WORDS)      // 9216
#define NSTAGE 3
#define SMEM_MAIN_BYTES (NSTAGE * STAGE_WORDS * 4)  // 110592

// ---------------------------------------------------------------------------
// City GEMM (fp16 mma): g_cbuf[m*D + n] = static @ W_city^T + b_city
// ---------------------------------------------------------------------------
__global__ __launch_bounds__(256, 2) void city_gemm(
    const __half* __restrict__ A,    // [N_DIM, K_DIM]
    const __half* __restrict__ W,    // [D_DIM, K_DIM]
    const float* __restrict__ bias)  // [D_DIM]
{
    constexpr int KD = K_DIM;
    constexpr int NCHUNK = KD / BK_T;   // 4

    extern __shared__ uint32_t smem[];
    const int tid  = threadIdx.x;
    const int wid  = tid >> 5;
    const int lane = tid & 31;
    const int wm   = wid & 3;
    const int wn   = wid >> 2;
    const int g    = lane >> 2;
    const int t    = lane & 3;

    const int bm = blockIdx.y * BM_T;
    const int bn = blockIdx.x * BN_T;

    const __half* Arow = A + (size_t)bm * KD;
    const __half* Wrow = W + (size_t)bn * KD;
    const uint32_t smem_b = smem_u32(smem);

    float acc[2][8][4];
    #pragma unroll
    for (int i = 0; i < 2; i++)
        #pragma unroll
        for (int j = 0; j < 8; j++)
            #pragma unroll
            for (int c = 0; c < 4; c++) acc[i][j][c] = 0.0f;

    auto prefetch = [&](int k0, int buf) {
        const uint32_t a_s = smem_b + (uint32_t)(buf * STAGE_WORDS) * 4u;
        const uint32_t b_s = a_s + A_WORDS * 4u;
        #pragma unroll
        for (int s = 0; s < 4; s++) {
            int id = tid + s * 256;
            int r  = id >> 3;
            int c16 = id & 7;
            cp_async16(a_s + (uint32_t)(r * 144 + c16 * 16),
                       Arow + (size_t)r * KD + k0 + c16 * 8);
        }
        #pragma unroll
        for (int s = 0; s < 4; s++) {
            int id = tid + s * 256;
            int r  = id >> 3;
            int c16 = id & 7;
            cp_async16(b_s + (uint32_t)(r * 144 + c16 * 16),
                       Wrow + (size_t)r * KD + k0 + c16 * 8);
        }
    };

    prefetch(0, 0);
    asm volatile("cp.async.commit_group;" ::: "memory");
    prefetch(BK_T, 1);
    asm volatile("cp.async.commit_group;" ::: "memory");

    #pragma unroll
    for (int k = 0; k < NCHUNK; k++) {
        if (k + 1 < NCHUNK) {
            asm volatile("cp.async.wait_group 1;" ::: "memory");
        } else {
            asm volatile("cp.async.wait_group 0;" ::: "memory");
        }
        __syncthreads();
        if (k + 2 < NCHUNK) {
            prefetch((k + 2) * BK_T, (k + 2) % NSTAGE);
            asm volatile("cp.async.commit_group;" ::: "memory");
        }

        const uint32_t* As32 = smem + (k % NSTAGE) * STAGE_WORDS;
        const uint32_t* Bs32 = As32 + A_WORDS;

        #pragma unroll
        for (int ks = 0; ks < 4; ks++) {
            uint32_t af[2][4];
            #pragma unroll
            for (int i = 0; i < 2; i++) {
                const uint32_t* ap = As32 + (wm * 32 + i * 16 + g) * STRIDE_W + ks * 8 + t;
                af[i][0] = ap[0];
                af[i][1] = ap[8 * STRIDE_W];
                af[i][2] = ap[4];
                af[i][3] = ap[8 * STRIDE_W + 4];
            }
            #pragma unroll
            for (int j = 0; j < 8; j++) {
                const uint32_t* bp = Bs32 + (wn * 64 + j * 8 + g) * STRIDE_W + ks * 8 + t;
                uint32_t b0 = bp[0];
                uint32_t b1 = bp[4];
                #pragma unroll
                for (int i = 0; i < 2; i++)
                    mma_f16(acc[i][j][0], acc[i][j][1], acc[i][j][2], acc[i][j][3],
                            af[i][0], af[i][1], af[i][2], af[i][3], b0, b1);
            }
        }
    }

    #pragma unroll
    for (int i = 0; i < 2; i++) {
        #pragma unroll
        for (int half = 0; half < 2; half++) {
            const int m = bm + wm * 32 + i * 16 + g + half * 8;
            float* orow = g_cbuf + (size_t)m * D_DIM;
            #pragma unroll
            for (int j = 0; j < 8; j++) {
                const int n = bn + wn * 64 + j * 8 + 2 * t;
                float2 o;
                o.x = acc[i][j][half * 2 + 0] + __ldg(bias + n);
                o.y = acc[i][j][half * 2 + 1] + __ldg(bias + n + 1);
                *(float2*)(orow + n) = o;
            }
        }
    }
}

// ---------------------------------------------------------------------------
// Main fused kernel: fp16 GEMM + bias + leaky + gate + cluster-LayerNorm.
// Cluster (8,1,1) along bn covers the full D=1024 per row-block; per-row
// stats are all-reduced across the 8 CTAs via DSMEM.
// SMEM reuse after MMA loop:
//   [0,       8192)  slots[8][128] float2   (per-rank partials, DSMEM targets)
//   [8192,   10240)  partial[2][128] float2 (per-wn local partials)
//   [10240,  11264)  stats[128] float2      (mean, rstd)
// ---------------------------------------------------------------------------
__global__ __launch_bounds__(256, 2) __cluster_dims__(8, 1, 1)
void main_gemm_fused(
    const __half* __restrict__ A,    // [M_MAIN, F_DIM]
    const __half* __restrict__ W,    // [D_DIM, F_DIM]
    const float* __restrict__ bias,  // [D_DIM]
    const float* __restrict__ gamma, // [D_DIM]
    const float* __restrict__ beta,  // [D_DIM]
    float* __restrict__ out)         // [M_MAIN, D_DIM]
{
    constexpr int KD = F_DIM;
    constexpr int NCHUNK = KD / BK_T;   // 8

    extern __shared__ uint32_t smem[];
    const int tid  = threadIdx.x;
    const int wid  = tid >> 5;
    const int lane = tid & 31;
    const int wm   = wid & 3;
    const int wn   = wid >> 2;
    const int g    = lane >> 2;
    const int t    = lane & 3;

    const int bm = blockIdx.y * BM_T;
    const int bn = blockIdx.x * BN_T;

    const __half* Arow = A + (size_t)bm * KD;
    const __half* Wrow = W + (size_t)bn * KD;
    const uint32_t smem_b = smem_u32(smem);

    float acc[2][8][4];
    #pragma unroll
    for (int i = 0; i < 2; i++)
        #pragma unroll
        for (int j = 0; j < 8; j++)
            #pragma unroll
            for (int c = 0; c < 4; c++) acc[i][j][c] = 0.0f;

    auto prefetch = [&](int k0, int buf) {
        const uint32_t a_s = smem_b + (uint32_t)(buf * STAGE_WORDS) * 4u;
        const uint32_t b_s = a_s + A_WORDS * 4u;
        #pragma unroll
        for (int s = 0; s < 4; s++) {
            int id = tid + s * 256;
            int r  = id >> 3;
            int c16 = id & 7;
            cp_async16(a_s + (uint32_t)(r * 144 + c16 * 16),
                       Arow + (size_t)r * KD + k0 + c16 * 8);
        }
        #pragma unroll
        for (int s = 0; s < 4; s++) {
            int id = tid + s * 256;
            int r  = id >> 3;
            int c16 = id & 7;
            cp_async16(b_s + (uint32_t)(r * 144 + c16 * 16),
                       Wrow + (size_t)r * KD + k0 + c16 * 8);
        }
    };

    prefetch(0, 0);
    asm volatile("cp.async.commit_group;" ::: "memory");
    prefetch(BK_T, 1);
    asm volatile("cp.async.commit_group;" ::: "memory");

    #pragma unroll
    for (int k = 0; k < NCHUNK; k++) {
        if (k + 1 < NCHUNK) {
            asm volatile("cp.async.wait_group 1;" ::: "memory");
        } else {
            asm volatile("cp.async.wait_group 0;" ::: "memory");
        }
        __syncthreads();
        if (k + 2 < NCHUNK) {
            prefetch((k + 2) * BK_T, (k + 2) % NSTAGE);
            asm volatile("cp.async.commit_group;" ::: "memory");
        }

        const uint32_t* As32 = smem + (k % NSTAGE) * STAGE_WORDS;
        const uint32_t* Bs32 = As32 + A_WORDS;

        #pragma unroll
        for (int ks = 0; ks < 4; ks++) {
            uint32_t af[2][4];
            #pragma unroll
            for (int i = 0; i < 2; i++) {
                const uint32_t* ap = As32 + (wm * 32 + i * 16 + g) * STRIDE_W + ks * 8 + t;
                af[i][0] = ap[0];
                af[i][1] = ap[8 * STRIDE_W];
                af[i][2] = ap[4];
                af[i][3] = ap[8 * STRIDE_W + 4];
            }
            #pragma unroll
            for (int j = 0; j < 8; j++) {
                const uint32_t* bp = Bs32 + (wn * 64 + j * 8 + g) * STRIDE_W + ks * 8 + t;
                uint32_t b0 = bp[0];
                uint32_t b1 = bp[4];
                #pragma unroll
                for (int i = 0; i < 2; i++)
                    mma_f16(acc[i][j][0], acc[i][j][1], acc[i][j][2], acc[i][j][3],
                            af[i][0], af[i][1], af[i][2], af[i][3], b0, b1);
            }
        }
    }

    // ---- Epilogue phase 1: bias + leaky + gate (store back into acc),
    //      per-row partial sums reduced over this CTA's 128 columns. ----
    float2* slots   = (float2*)smem;                    // [8][128]
    float2* partial = (float2*)(smem + 2048);           // [2][128]
    float2* stats   = (float2*)(smem + 2048 + 512);     // [128]

    #pragma unroll
    for (int i = 0; i < 2; i++) {
        #pragma unroll
        for (int half = 0; half < 2; half++) {
            const int row_local = wm * 32 + i * 16 + half * 8 + g;
            const int m = bm + row_local;
            const float* gate = g_cbuf + (size_t)(m & (N_DIM - 1)) * D_DIM;
            float s = 0.0f, ss = 0.0f;
            #pragma unroll
            for (int j = 0; j < 8; j++) {
                const int n = bn + wn * 64 + j * 8 + 2 * t;
                float v0 = acc[i][j][half * 2 + 0] + __ldg(bias + n);
                float v1 = acc[i][j][half * 2 + 1] + __ldg(bias + n + 1);
                v0 = (v0 >= 0.0f) ? v0 : 0.2f * v0;
                v1 = (v1 >= 0.0f) ? v1 : 0.2f * v1;
                v0 *= __ldg(gate + n);
                v1 *= __ldg(gate + n + 1);
                acc[i][j][half * 2 + 0] = v0;
                acc[i][j][half * 2 + 1] = v1;
                s += v0 + v1;
                ss += v0 * v0 + v1 * v1;
            }
            // reduce across the 4 t-lanes (lane bits 0..1)
            s  += __shfl_xor_sync(0xFFFFFFFFu, s, 1);
            ss += __shfl_xor_sync(0xFFFFFFFFu, ss, 1);
            s  += __shfl_xor_sync(0xFFFFFFFFu, s, 2);
            ss += __shfl_xor_sync(0xFFFFFFFFu, ss, 2);
            if (t == 0) {
                float2 p; p.x = s; p.y = ss;
                partial[wn * 128 + row_local] = p;
            }
        }
    }
    __syncthreads();

    // All CTAs in the cluster are done reading stage SMEM and writing local
    // partials; only now may peers write into our slots area.
    CLUSTER_ARRIVE();
    CLUSTER_WAIT();

    const uint32_t rank = cluster_rank();
    if (tid < 128) {
        float2 p0 = partial[tid];
        float2 p1 = partial[128 + tid];
        float s = p0.x + p1.x, ss = p0.y + p1.y;
        const uint32_t slot_addr = smem_b + (rank * 128 + (uint32_t)tid) * 8u;
        #pragma unroll
        for (uint32_t r = 0; r < 8; r++)
            dsmem_st_f32x2(slot_addr, r, s, ss);
    }

    CLUSTER_ARRIVE();
    CLUSTER_WAIT();

    if (tid < 128) {
        float s = 0.0f, ss = 0.0f;
        #pragma unroll
        for (int r = 0; r < 8; r++) {
            float2 p = slots[r * 128 + tid];
            s += p.x; ss += p.y;
        }
        const float inv_d = 1.0f / (float)D_DIM;
        float mean = s * inv_d;
        float var  = ss * inv_d - mean * mean;
        float2 st2; st2.x = mean; st2.y = rsqrtf(var + 1e-5f);
        stats[tid] = st2;
    }
    __syncthreads();

    // ---- Epilogue phase 2: normalize + affine + final store. ----
    #pragma unroll
    for (int i = 0; i < 2; i++) {
        #pragma unroll
        for (int half = 0; half < 2; half++) {
            const int row_local = wm * 32 + i * 16 + half * 8 + g;
            const int m = bm + row_local;
            float2 st2 = stats[row_local];
            const float mean = st2.x, rstd = st2.y;
            float* orow = out + (size_t)m * D_DIM;
            #pragma unroll
            for (int j = 0; j < 8; j++) {
                const int n = bn + wn * 64 + j * 8 + 2 * t;
                float2 o;
                o.x = (acc[i][j][half * 2 + 0] - mean) * rstd * __ldg(gamma + n)
                    + __ldg(beta + n);
                o.y = (acc[i][j][half * 2 + 1] - mean) * rstd * __ldg(gamma + n + 1)
                    + __ldg(beta + n + 1);
                *(float2*)(orow + n) = o;
            }
        }
    }
}

// ---------------------------------------------------------------------------
extern "C" void kernel_launch(void* const* d_in, const int* in_sizes, int n_in,
                              void* d_out, int out_size)
{
    const float* input  = (const float*)d_in[0];  // [B, N, F]
    const float* stat   = (const float*)d_in[1];  // [N, K]
    const float* W_feat = (const float*)d_in[2];  // [D, F]
    const float* b_feat = (const float*)d_in[3];  // [D]
    const float* W_city = (const float*)d_in[4];  // [D, K]
    const float* b_city = (const float*)d_in[5];  // [D]
    const float* gamma  = (const float*)d_in[6];  // [D]
    const float* beta   = (const float*)d_in[7];  // [D]
    float* out = (float*)d_out;                   // [B, N, D]

    cudaFuncSetAttribute(main_gemm_fused,
                         cudaFuncAttributeMaxDynamicSharedMemorySize,
                         SMEM_MAIN_BYTES);
    cudaFuncSetAttribute(city_gemm,
                         cudaFuncAttributeMaxDynamicSharedMemorySize,
                         SMEM_MAIN_BYTES);

    __half *a16, *wf16, *st16, *wc16;
    cudaGetSymbolAddress((void**)&a16,  g_a16);
    cudaGetSymbolAddress((void**)&wf16, g_wf16);
    cudaGetSymbolAddress((void**)&st16, g_st16);
    cudaGetSymbolAddress((void**)&wc16, g_wc16);

    // 0) fp32 -> fp16 pre-passes
    {
        int n4 = (M_MAIN * F_DIM) / 4;   // 8388608
        f2h_kernel<<<(n4 + 1023) / 1024, 256>>>(input, a16, n4);
        int tot4 = WF_N4 + ST_N4 + WC_N4;  // 327680
        f2h3_kernel<<<(tot4 + 1023) / 1024, 256>>>(W_feat, wf16, stat, st16,
                                                   W_city, wc16);
    }
    // 1) city embed: g_cbuf = static @ W_city^T + b_city
    {
        dim3 grid(D_DIM / BN_T, N_DIM / BM_T);   // (8, 16)
        city_gemm<<<grid, 256, SMEM_MAIN_BYTES>>>(st16, wc16, b_city);
    }
    // 2) main fused: out = LN(leaky(input @ W_feat^T + b) * gate) * gamma + beta
    {
        dim3 grid(D_DIM / BN_T, M_MAIN / BM_T);  // (8, 512), cluster (8,1,1)
        main_gemm_fused<<<grid, 256, SMEM_MAIN_BYTES>>>(a16, wf16, b_feat,
                                                        gamma, beta, out);
    }
}